// round 9
// baseline (speedup 1.0000x reference)
#include <cuda_runtime.h>

// ort = mean(x1 @ x2^T) = dot(colsum(x1), colsum(x2)) / N^2
// N = 8192 rows, D = 1024 cols. 64 MB read, pure HBM-bound.
// Single fused kernel. Key change vs R7: 256-bit loads (ld.global.nc.v8.f32,
// sm_10x) double the bytes per outstanding LSU request; 512-thread CTAs at
// 2/SM give a 64-reg budget so 2 v8 loads + 16 accumulators live in regs.
// Device globals are zero-init at load; last block restores them to zero.

#define D 1024
#define GRID 296
#define TPB 512                          // 4 row-groups x 128 col-threads

__device__ float g_colsum[2 * D];        // zero-initialized; invariant
__device__ unsigned int g_done = 0;      // completion counter; invariant

struct float8 { float v[8]; };

__device__ __forceinline__ float8 ldg256(const float* __restrict__ p) {
    float8 r;
    asm("ld.global.nc.v8.f32 {%0,%1,%2,%3,%4,%5,%6,%7}, [%8];"
        : "=f"(r.v[0]), "=f"(r.v[1]), "=f"(r.v[2]), "=f"(r.v[3]),
          "=f"(r.v[4]), "=f"(r.v[5]), "=f"(r.v[6]), "=f"(r.v[7])
        : "l"(p));
    return r;
}

__global__ __launch_bounds__(TPB, 2) void fused_kernel(
    const float* __restrict__ x1,
    const float* __restrict__ x2,
    float* __restrict__ out,
    int nrows, double inv_n2) {

    const int t = threadIdx.x;
    const int g = t >> 7;                // row group 0..3
    const int c = t & 127;               // owns cols [8c, 8c+8)

    // Balanced contiguous stripes: 27-28 rows per block.
    const int r0 = (int)(((size_t)blockIdx.x * nrows) / GRID);
    const int r1 = (int)(((size_t)(blockIdx.x + 1) * nrows) / GRID);

    float a1[8], a2[8];
    #pragma unroll
    for (int i = 0; i < 8; i++) { a1[i] = 0.f; a2[i] = 0.f; }

    #pragma unroll 7
    for (int r = r0 + g; r < r1; r += 4) {
        const size_t base = (size_t)r * D + 8 * c;
        float8 v1 = ldg256(x1 + base);   // two independent 32B requests
        float8 v2 = ldg256(x2 + base);
        #pragma unroll
        for (int i = 0; i < 8; i++) { a1[i] += v1.v[i]; a2[i] += v2.v[i]; }
    }

    // ---- single-pass smem reduce across row-groups ----
    __shared__ float s[4 * 2 * D];       // 32 KB: [group][x1 cols | x2 cols]
    float4* sv = (float4*)(s + g * 2 * D + 8 * c);
    sv[0] = make_float4(a1[0], a1[1], a1[2], a1[3]);
    sv[1] = make_float4(a1[4], a1[5], a1[6], a1[7]);
    float4* sv2 = (float4*)(s + g * 2 * D + D + 8 * c);
    sv2[0] = make_float4(a2[0], a2[1], a2[2], a2[3]);
    sv2[1] = make_float4(a2[4], a2[5], a2[6], a2[7]);
    __syncthreads();

    {   // each thread reduces 4 of the 2048 columns across the 4 groups
        const float4* sf = (const float4*)s;            // 512 float4 per group
        float4 v = sf[t];
        float4 b = sf[512 + t];
        float4 d2 = sf[1024 + t];
        float4 e = sf[1536 + t];
        v.x += b.x + d2.x + e.x;
        v.y += b.y + d2.y + e.y;
        v.z += b.z + d2.z + e.z;
        v.w += b.w + d2.w + e.w;
        atomicAdd(&g_colsum[4 * t + 0], v.x);
        atomicAdd(&g_colsum[4 * t + 1], v.y);
        atomicAdd(&g_colsum[4 * t + 2], v.z);
        atomicAdd(&g_colsum[4 * t + 3], v.w);
    }

    // Completion protocol: last block finishes the reduction.
    __shared__ bool s_last;
    __threadfence();
    __syncthreads();
    if (t == 0)
        s_last = (atomicAdd(&g_done, 1u) == GRID - 1);
    __syncthreads();
    if (!s_last) return;

    // ---- last block only: dot(colsum1, colsum2) / N^2 ----
    double v = (double)g_colsum[t] * (double)g_colsum[D + t]
             + (double)g_colsum[t + 512] * (double)g_colsum[D + t + 512];

    __shared__ double sred[TPB / 32];
    #pragma unroll
    for (int o = 16; o > 0; o >>= 1)
        v += __shfl_down_sync(0xffffffffu, v, o);
    if ((t & 31) == 0) sred[t >> 5] = v;
    __syncthreads();
    if (t < 32) {
        double w = (t < TPB / 32) ? sred[t] : 0.0;
        #pragma unroll
        for (int o = 8; o > 0; o >>= 1)
            w += __shfl_down_sync(0xffffffffu, w, o);
        if (t == 0) out[0] = (float)(w * inv_n2);
    }

    // Restore invariants for the next graph replay.
    #pragma unroll
    for (int i = t; i < 2 * D; i += TPB)
        g_colsum[i] = 0.0f;
    if (t == 0) g_done = 0u;
}

extern "C" void kernel_launch(void* const* d_in, const int* in_sizes, int n_in,
                              void* d_out, int out_size) {
    const float* x1 = (const float*)d_in[0];
    const float* x2 = (const float*)d_in[1];
    float* out = (float*)d_out;

    const int nrows = in_sizes[0] / D;   // 8192
    const double inv_n2 = 1.0 / ((double)nrows * (double)nrows);

    fused_kernel<<<GRID, TPB>>>(x1, x2, out, nrows, inv_n2);
}

// round 11
// speedup vs baseline: 1.3950x; 1.3950x over previous
#include <cuda_runtime.h>
#include <cstdint>

// ort = mean(x1 @ x2^T) = dot(colsum(x1), colsum(x2)) / N^2
// N = 8192 rows, D = 1024 cols. 64 MB read, pure HBM-bound.
// R10: cp.async (LDGSTS) pipeline into shared memory. Register file no longer
// bounds MLP: 2 CTAs/SM x 2 pending 32KB stages = 128KB in flight per SM,
// ~6x the latency-BW product. Consumer reduces from smem with 2 regs.
// Device globals zero-init at load; last block restores them (graph-safe).

#define D 1024
#define GRID 296
#define TPB 1024
#define DEPTH 3
#define CH_ROWS 4
#define STAGE_FLOATS (2 * CH_ROWS * D)           // 8192 floats = 32 KB/stage
#define SMEM_BYTES (DEPTH * STAGE_FLOATS * 4)    // 96 KB

__device__ float g_colsum[2 * D];        // zero-initialized; invariant
__device__ unsigned int g_done = 0;      // completion counter; invariant

__device__ __forceinline__ void cp16(uint32_t saddr, const float* g) {
    asm volatile("cp.async.cg.shared.global [%0], [%1], 16;"
                 :: "r"(saddr), "l"(g));
}

__global__ __launch_bounds__(TPB, 2) void fused_kernel(
    const float* __restrict__ x1,
    const float* __restrict__ x2,
    float* __restrict__ out,
    int nrows, double inv_n2) {

    extern __shared__ float s[];         // [DEPTH][2][CH_ROWS][D]
    const int t = threadIdx.x;
    const int rr = t >> 8;               // row-in-chunk 0..3
    const int seg = t & 255;             // 16B segment within 4KB row

    // Balanced contiguous stripes (27-28 rows).
    const int r0 = (int)(((size_t)blockIdx.x * nrows) / GRID);
    const int r1 = (int)(((size_t)(blockIdx.x + 1) * nrows) / GRID);
    const int nch = (r1 - r0 + CH_ROWS - 1) / CH_ROWS;   // 7

    const uint32_t sbase = (uint32_t)__cvta_generic_to_shared(s);

    // Issue chunk i (always commits a group, possibly empty, to keep
    // per-thread wait_group counts aligned).
    auto issue = [&](int i) {
        const int row = r0 + i * CH_ROWS + rr;
        if (row < r1) {
            const size_t goff = (size_t)row * D + seg * 4;
            const int buf = i % DEPTH;
            uint32_t d1 = sbase + (uint32_t)(buf * STAGE_FLOATS + rr * D) * 4u
                        + seg * 16u;
            uint32_t d2 = d1 + (uint32_t)(CH_ROWS * D) * 4u;
            cp16(d1, x1 + goff);
            cp16(d2, x2 + goff);
        }
        asm volatile("cp.async.commit_group;");
    };

    // Prologue: fill the pipeline.
    issue(0); issue(1); issue(2);        // DEPTH == 3

    float acc1 = 0.f, acc2 = 0.f;

    for (int i = 0; i < nch; i++) {
        asm volatile("cp.async.wait_group %0;" :: "n"(DEPTH - 1));
        __syncthreads();                 // cross-thread smem visibility

        const int buf = i % DEPTH;
        const float* p1 = s + buf * STAGE_FLOATS;
        const float* p2 = p1 + CH_ROWS * D;
        const int cb = r0 + i * CH_ROWS;
        #pragma unroll
        for (int k = 0; k < CH_ROWS; k++) {
            if (cb + k < r1) {
                acc1 += p1[k * D + t];
                acc2 += p2[k * D + t];
            }
        }
        __syncthreads();                 // reads done before buffer reuse
        issue(i + DEPTH);
    }

    // One atomic per column per input (296 x 2048 spread-address total).
    atomicAdd(&g_colsum[t], acc1);
    atomicAdd(&g_colsum[D + t], acc2);

    // Completion protocol: last block finishes the reduction.
    __shared__ bool s_last;
    __threadfence();
    __syncthreads();
    if (t == 0)
        s_last = (atomicAdd(&g_done, 1u) == GRID - 1);
    __syncthreads();
    if (!s_last) return;

    // ---- last block only: dot(colsum1, colsum2) / N^2 ----
    double v = (double)g_colsum[t] * (double)g_colsum[D + t];

    __shared__ double sred[TPB / 32];
    #pragma unroll
    for (int o = 16; o > 0; o >>= 1)
        v += __shfl_down_sync(0xffffffffu, v, o);
    if ((t & 31) == 0) sred[t >> 5] = v;
    __syncthreads();
    if (t < 32) {
        double w = sred[t];              // TPB/32 == 32 exactly
        #pragma unroll
        for (int o = 16; o > 0; o >>= 1)
            w += __shfl_down_sync(0xffffffffu, w, o);
        if (t == 0) out[0] = (float)(w * inv_n2);
    }

    // Restore invariants for the next graph replay.
    g_colsum[t] = 0.0f;
    g_colsum[D + t] = 0.0f;
    if (t == 0) g_done = 0u;
}

extern "C" void kernel_launch(void* const* d_in, const int* in_sizes, int n_in,
                              void* d_out, int out_size) {
    const float* x1 = (const float*)d_in[0];
    const float* x2 = (const float*)d_in[1];
    float* out = (float*)d_out;

    const int nrows = in_sizes[0] / D;   // 8192
    const double inv_n2 = 1.0 / ((double)nrows * (double)nrows);

    cudaFuncSetAttribute(fused_kernel,
                         cudaFuncAttributeMaxDynamicSharedMemorySize,
                         SMEM_BYTES);
    fused_kernel<<<GRID, TPB, SMEM_BYTES>>>(x1, x2, out, nrows, inv_n2);
}